// round 1
// baseline (speedup 1.0000x reference)
#include <cuda_runtime.h>
#include <cstdint>

#define B_ 2
#define S_ 2048
#define D_ 1024
#define H_ 16
#define U_ 64
#define QSCALE 0.125f   /* 1/sqrt(64) */

// scratch for attention output (16 MB) — static __device__, no allocation
__device__ float g_att[(size_t)B_ * S_ * D_];

// ---------------------------------------------------------------------------
// fast exp: degree-5 Taylor for 2^f on [-0.5,0.5] + exponent bit-add.
// Avoids MUFU (rt=8/SMSP would serialize 134M softmax exps into ~1ms).
// rel err ~2e-6, valid for x <= 0 (clamped at -80 -> exp ~ 1.8e-35, no denorm).
// ---------------------------------------------------------------------------
__device__ __forceinline__ float fast_exp(float x) {
    x = fmaxf(x, -80.0f);
    const float L2E = 1.4426950408889634f;
    float t  = fmaf(x, L2E, 12582912.0f);     // round-to-nearest int in low bits
    int   n  = __float_as_int(t);             // (0x4B400000 + nint); low 9 bits of base = 0
    float yr = t - 12582912.0f;               // rounded integer as float
    float f  = fmaf(x, L2E, -yr);             // frac in [-0.5, 0.5]
    float p  =        1.3333558146e-3f;
    p = fmaf(p, f,    9.6181291076e-3f);
    p = fmaf(p, f,    5.5504108664e-2f);
    p = fmaf(p, f,    2.4022650696e-1f);
    p = fmaf(p, f,    6.9314718056e-1f);
    p = fmaf(p, f,    1.0f);
    return __int_as_float(__float_as_int(p) + (n << 23));  // p * 2^nint
}

// ---------------------------------------------------------------------------
// Fused attention: per CTA = one (b, h, 64-query tile).
// Flash-style online softmax over 32 key tiles of 64.
// 256 threads as 16x16, each owns a 4x4 micro-tile.
// Shared (dynamic, ~70KB): Qs,Ks,Vs,Ps each 64x68 fp32 (+4 pad keeps float4
// alignment AND shifts banks between rows), kb[64] key-bias.
// ---------------------------------------------------------------------------
__global__ void __launch_bounds__(256) attn_kernel(
        const float* __restrict__ q,
        const float* __restrict__ k,
        const float* __restrict__ v,
        const float* __restrict__ mask) {
    extern __shared__ float sm[];
    float* Qs = sm;                 // 64*68
    float* Ks = Qs + 64 * 68;
    float* Vs = Ks + 64 * 68;
    float* Ps = Vs + 64 * 68;
    float* kb = Ps + 64 * 68;       // 64

    const int b  = blockIdx.z;
    const int h  = blockIdx.y;
    const int i0 = blockIdx.x * 64;
    const int tid = threadIdx.x;
    const int ty = tid >> 4;        // 0..15 : query-row group (rows 4*ty..4*ty+3)
    const int tx = tid & 15;        // 0..15 : col group

    const size_t bh_off = (size_t)b * S_ * D_ + (size_t)h * U_;

    // ---- load Q tile (pre-scaled by 1/sqrt(U)) ----
    {
        const int r  = tid >> 4;          // 16 rows/pass, 4 passes
        const int c  = (tid & 15) * 4;
        #pragma unroll
        for (int p = 0; p < 4; p++) {
            int row = r + p * 16;
            float4 t4 = *(const float4*)(q + bh_off + (size_t)(i0 + row) * D_ + c);
            t4.x *= QSCALE; t4.y *= QSCALE; t4.z *= QSCALE; t4.w *= QSCALE;
            *(float4*)(Qs + row * 68 + c) = t4;
        }
    }

    float acc[4][4] = {};
    float mrow[4] = {-1e30f, -1e30f, -1e30f, -1e30f};
    float lrow[4] = {};

    for (int jt = 0; jt < S_ / 64; jt++) {
        const int j0 = jt * 64;
        __syncthreads();   // prev PV done (iter 0: Q stores done)

        // ---- load K, V tiles + key bias ----
        {
            const int r = tid >> 4;
            const int c = (tid & 15) * 4;
            #pragma unroll
            for (int p = 0; p < 4; p++) {
                int row = r + p * 16;
                *(float4*)(Ks + row * 68 + c) =
                    *(const float4*)(k + bh_off + (size_t)(j0 + row) * D_ + c);
                *(float4*)(Vs + row * 68 + c) =
                    *(const float4*)(v + bh_off + (size_t)(j0 + row) * D_ + c);
            }
            if (tid < 64)
                kb[tid] = (1.0f - mask[(size_t)b * S_ + j0 + tid]) * 10000.0f;
        }
        __syncthreads();

        // ---- S = Q K^T  (4x4 micro-tile, float4 over u) ----
        float s[4][4] = {};
        #pragma unroll
        for (int u4 = 0; u4 < 16; u4++) {
            float4 q4[4], k4[4];
            #pragma unroll
            for (int i = 0; i < 4; i++)
                q4[i] = *(float4*)(Qs + (4 * ty + i) * 68 + 4 * u4);
            #pragma unroll
            for (int j = 0; j < 4; j++)
                k4[j] = *(float4*)(Ks + (4 * tx + j) * 68 + 4 * u4);
            #pragma unroll
            for (int i = 0; i < 4; i++)
                #pragma unroll
                for (int j = 0; j < 4; j++) {
                    s[i][j] = fmaf(q4[i].x, k4[j].x, s[i][j]);
                    s[i][j] = fmaf(q4[i].y, k4[j].y, s[i][j]);
                    s[i][j] = fmaf(q4[i].z, k4[j].z, s[i][j]);
                    s[i][j] = fmaf(q4[i].w, k4[j].w, s[i][j]);
                }
        }

        // ---- online softmax (row reductions across the 16-lane tx group) ----
        float kbv[4];
        #pragma unroll
        for (int j = 0; j < 4; j++) kbv[j] = kb[4 * tx + j];

        #pragma unroll
        for (int i = 0; i < 4; i++) {
            #pragma unroll
            for (int j = 0; j < 4; j++) s[i][j] -= kbv[j];
            float rm = fmaxf(fmaxf(s[i][0], s[i][1]), fmaxf(s[i][2], s[i][3]));
            #pragma unroll
            for (int o = 8; o > 0; o >>= 1)
                rm = fmaxf(rm, __shfl_xor_sync(0xffffffffu, rm, o));
            const float mnew  = fmaxf(mrow[i], rm);
            const float alpha = fast_exp(mrow[i] - mnew);
            float rs = 0.0f;
            #pragma unroll
            for (int j = 0; j < 4; j++) {
                float pv = fast_exp(s[i][j] - mnew);
                s[i][j] = pv;
                rs += pv;
            }
            #pragma unroll
            for (int o = 8; o > 0; o >>= 1)
                rs += __shfl_xor_sync(0xffffffffu, rs, o);
            lrow[i] = lrow[i] * alpha + rs;
            mrow[i] = mnew;
            #pragma unroll
            for (int j = 0; j < 4; j++) acc[i][j] *= alpha;
        }

        // ---- stage P ----
        #pragma unroll
        for (int i = 0; i < 4; i++)
            *(float4*)(Ps + (4 * ty + i) * 68 + 4 * tx) =
                make_float4(s[i][0], s[i][1], s[i][2], s[i][3]);
        __syncthreads();

        // ---- O += P V  (float4 over key dim) ----
        #pragma unroll
        for (int k4i = 0; k4i < 16; k4i++) {
            float4 p4[4], v4[4];
            #pragma unroll
            for (int i = 0; i < 4; i++)
                p4[i] = *(float4*)(Ps + (4 * ty + i) * 68 + 4 * k4i);
            #pragma unroll
            for (int t = 0; t < 4; t++)
                v4[t] = *(float4*)(Vs + (4 * k4i + t) * 68 + 4 * tx);
            #pragma unroll
            for (int i = 0; i < 4; i++) {
                acc[i][0] = fmaf(p4[i].x, v4[0].x, acc[i][0]);
                acc[i][1] = fmaf(p4[i].x, v4[0].y, acc[i][1]);
                acc[i][2] = fmaf(p4[i].x, v4[0].z, acc[i][2]);
                acc[i][3] = fmaf(p4[i].x, v4[0].w, acc[i][3]);
                acc[i][0] = fmaf(p4[i].y, v4[1].x, acc[i][0]);
                acc[i][1] = fmaf(p4[i].y, v4[1].y, acc[i][1]);
                acc[i][2] = fmaf(p4[i].y, v4[1].z, acc[i][2]);
                acc[i][3] = fmaf(p4[i].y, v4[1].w, acc[i][3]);
                acc[i][0] = fmaf(p4[i].z, v4[2].x, acc[i][0]);
                acc[i][1] = fmaf(p4[i].z, v4[2].y, acc[i][1]);
                acc[i][2] = fmaf(p4[i].z, v4[2].z, acc[i][2]);
                acc[i][3] = fmaf(p4[i].z, v4[2].w, acc[i][3]);
                acc[i][0] = fmaf(p4[i].w, v4[3].x, acc[i][0]);
                acc[i][1] = fmaf(p4[i].w, v4[3].y, acc[i][1]);
                acc[i][2] = fmaf(p4[i].w, v4[3].z, acc[i][2]);
                acc[i][3] = fmaf(p4[i].w, v4[3].w, acc[i][3]);
            }
        }
    }

    // ---- normalize and write attended ----
    #pragma unroll
    for (int i = 0; i < 4; i++) {
        const float inv = 1.0f / lrow[i];
        float4 o4 = make_float4(acc[i][0] * inv, acc[i][1] * inv,
                                acc[i][2] * inv, acc[i][3] * inv);
        *(float4*)(g_att + ((size_t)b * S_ + i0 + 4 * ty + i) * D_
                          + (size_t)h * U_ + 4 * tx) = o4;
    }
}

// ---------------------------------------------------------------------------
// Output projection: out[M=4096, N=1024] = g_att @ W_o[1024,1024]
// 64x64 tile, KT=32, 256 threads, 4x4 micro-tile. A staged transposed
// (As[k][m]) so the inner loop is 2x LDS.128 per 16 FMA.
// ---------------------------------------------------------------------------
__global__ void __launch_bounds__(256) proj_kernel(
        const float* __restrict__ W, float* __restrict__ out) {
    __shared__ float As[32][68];    // [k][m]
    __shared__ float Bs[32][68];    // [k][n]

    const int n0 = blockIdx.x * 64;
    const int m0 = blockIdx.y * 64;
    const int tid = threadIdx.x;
    const int ty = tid >> 4;
    const int tx = tid & 15;

    const float* A = g_att;
    float acc[4][4] = {};

    for (int k0 = 0; k0 < D_; k0 += 32) {
        __syncthreads();
        // A tile 64x32, stored transposed
        {
            const int m  = tid >> 3;           // 0..31
            const int kk = (tid & 7) * 4;      // 0..28
            #pragma unroll
            for (int p = 0; p < 2; p++) {
                int mm = m + p * 32;
                float4 a4 = *(const float4*)(A + (size_t)(m0 + mm) * D_ + k0 + kk);
                As[kk + 0][mm] = a4.x;
                As[kk + 1][mm] = a4.y;
                As[kk + 2][mm] = a4.z;
                As[kk + 3][mm] = a4.w;
            }
        }
        // B tile 32x64, natural layout
        {
            const int kr = tid >> 4;           // 0..15
            const int n  = (tid & 15) * 4;
            #pragma unroll
            for (int p = 0; p < 2; p++) {
                *(float4*)(&Bs[kr + p * 16][n]) =
                    *(const float4*)(W + (size_t)(k0 + kr + p * 16) * D_ + n0 + n);
            }
        }
        __syncthreads();

        #pragma unroll
        for (int kk = 0; kk < 32; kk++) {
            float4 a4 = *(float4*)&As[kk][4 * ty];
            float4 b4 = *(float4*)&Bs[kk][4 * tx];
            acc[0][0] = fmaf(a4.x, b4.x, acc[0][0]);
            acc[0][1] = fmaf(a4.x, b4.y, acc[0][1]);
            acc[0][2] = fmaf(a4.x, b4.z, acc[0][2]);
            acc[0][3] = fmaf(a4.x, b4.w, acc[0][3]);
            acc[1][0] = fmaf(a4.y, b4.x, acc[1][0]);
            acc[1][1] = fmaf(a4.y, b4.y, acc[1][1]);
            acc[1][2] = fmaf(a4.y, b4.z, acc[1][2]);
            acc[1][3] = fmaf(a4.y, b4.w, acc[1][3]);
            acc[2][0] = fmaf(a4.z, b4.x, acc[2][0]);
            acc[2][1] = fmaf(a4.z, b4.y, acc[2][1]);
            acc[2][2] = fmaf(a4.z, b4.z, acc[2][2]);
            acc[2][3] = fmaf(a4.z, b4.w, acc[2][3]);
            acc[3][0] = fmaf(a4.w, b4.x, acc[3][0]);
            acc[3][1] = fmaf(a4.w, b4.y, acc[3][1]);
            acc[3][2] = fmaf(a4.w, b4.z, acc[3][2]);
            acc[3][3] = fmaf(a4.w, b4.w, acc[3][3]);
        }
    }

    #pragma unroll
    for (int i = 0; i < 4; i++) {
        *(float4*)(out + (size_t)(m0 + 4 * ty + i) * D_ + n0 + 4 * tx) =
            make_float4(acc[i][0], acc[i][1], acc[i][2], acc[i][3]);
    }
}

extern "C" void kernel_launch(void* const* d_in, const int* in_sizes, int n_in,
                              void* d_out, int out_size) {
    const float* q    = (const float*)d_in[0];
    const float* k    = (const float*)d_in[1];
    const float* v    = (const float*)d_in[2];
    const float* mask = (const float*)d_in[3];
    const float* W    = (const float*)d_in[4];
    float* out = (float*)d_out;

    const int smem = (4 * 64 * 68 + 64) * (int)sizeof(float);   // 69,888 B
    cudaFuncSetAttribute(attn_kernel,
                         cudaFuncAttributeMaxDynamicSharedMemorySize, smem);

    dim3 g1(S_ / 64, H_, B_);           // (32, 16, 2) = 1024 CTAs
    attn_kernel<<<g1, 256, smem>>>(q, k, v, mask);

    dim3 g2(D_ / 64, (B_ * S_) / 64);   // (16, 64) = 1024 CTAs
    proj_kernel<<<g2, 256>>>(W, out);
}